// round 8
// baseline (speedup 1.0000x reference)
// R8: R5 (passed, 1936us) + ONE delta: MMA dependency-chain break in
// k_conv_mma (B preload + three independent passes). Everything else
// byte-identical to R5 to isolate the variable.
#include <cuda_runtime.h>
#include <cuda_fp16.h>
#include <math.h>
#include <stdint.h>

#define NB 8
#define NC 96
#define HH 128
#define WW 128
#define HW (HH*WW)
#define NPB (NC*HW)          // 1,572,864
#define NTOT (NB*NPB)
#define KK 9
#define CKK (NC*KK)          // 864
#define LL 1764              // 42*42 unfold positions

#define NPAIR 48             // ci pairs
#define NCHUNK 6             // 96/16
#define WFRAG_PER_CHUNK 3456             // 9*2*6*32 uint4
#define WFRAG_PER_B (NCHUNK*WFRAG_PER_CHUNK)   // 20736 uint4 per batch

// ---------------- scratch (device globals; no allocation) ----------------
__device__ float g_xr[NTOT];
__device__ float g_x1o[NTOT];
__device__ float g_key[NTOT];
__device__ float g_qry[NTOT];
__device__ float g_val[NTOT];
__device__ float g_y2p[NTOT];
__device__ float g_y1p[NTOT];
__device__ float g_attn[NB*NC*CKK];

// hi/lo packed inputs: [b][pair(48)][h][w] -> uint2 {hi2, lo2}
__device__ uint2 g_x1hl[NB*NPAIR*HW];
__device__ uint2 g_x2hl[NB*NPAIR*HW];
__device__ uint2 g_valhl[NB*NPAIR*HW];

// fragment-ordered weights (hi/lo f16), uint4 per lane
__device__ uint4 g_w1f[WFRAG_PER_B];
__device__ uint4 g_w2f[WFRAG_PER_B];
__device__ uint4 g_w3f[WFRAG_PER_B];
__device__ uint4 g_wc2f[WFRAG_PER_B];
__device__ uint4 g_attnf[NB*WFRAG_PER_B];

__device__ double g_sumx[NB];
__device__ double g_st[NB*5];      // pos, s1, q1, s2, q2
__device__ double g_lnacc[2*NB*2]; // [slot][b][{sum,sumsq}]
__device__ float  g_cst[NB*5];     // mean, avg1, k1, avg2, k2
__device__ float  g_lnc[NB*4];     // m1, inv1, m2, inv2

// ---------------- helpers ----------------
__device__ __forceinline__ double blockReduceD(double v, double* sm) {
    int t = threadIdx.x;
    __syncthreads();
    sm[t] = v;
    __syncthreads();
    for (int s = 128; s > 0; s >>= 1) {
        if (t < s) sm[t] += sm[t + s];
        __syncthreads();
    }
    return sm[0];
}

__device__ __forceinline__ unsigned packh2(__half a, __half b) {
    __half2 h = __halves2half2(a, b);
    return *reinterpret_cast<unsigned*>(&h);
}

// ---------------- stage 0: zero accumulators ----------------
__global__ void k_zero() {
    int i = threadIdx.x;
    if (i < NB) g_sumx[i] = 0.0;
    if (i < NB*5) g_st[i] = 0.0;
    if (i < 2*NB*2) g_lnacc[i] = 0.0;
}

// ---------------- stage 1: per-batch sum of x ----------------
__global__ __launch_bounds__(256) void k_sum_x(const float* __restrict__ x) {
    __shared__ double sm[256];
    int b = blockIdx.y, c = blockIdx.x;
    const float* p = x + (size_t)(b*NC + c)*HW;
    double s = 0.0;
    for (int i = threadIdx.x; i < HW; i += 256) s += (double)p[i];
    double r = blockReduceD(s, sm);
    if (threadIdx.x == 0) atomicAdd(&g_sumx[b], r);
}

// ---------------- stage 2: split stats over centered x ----------------
__global__ __launch_bounds__(256) void k_stats2(const float* __restrict__ x) {
    __shared__ double sm[256];
    int b = blockIdx.y, c = blockIdx.x;
    float m = (float)(g_sumx[b] / (double)NPB);
    const float* p = x + (size_t)(b*NC + c)*HW;
    double pos = 0, s1 = 0, q1 = 0, s2 = 0, q2 = 0;
    for (int i = threadIdx.x; i < HW; i += 256) {
        float xc = p[i] - m;
        if (xc > 0.f) { pos += 1.0; s1 += (double)xc; q1 += (double)xc*(double)xc; }
        else          { s2 += (double)xc; q2 += (double)xc*(double)xc; }
    }
    double r;
    r = blockReduceD(pos, sm); if (threadIdx.x == 0) atomicAdd(&g_st[b*5+0], r);
    r = blockReduceD(s1,  sm); if (threadIdx.x == 0) atomicAdd(&g_st[b*5+1], r);
    r = blockReduceD(q1,  sm); if (threadIdx.x == 0) atomicAdd(&g_st[b*5+2], r);
    r = blockReduceD(s2,  sm); if (threadIdx.x == 0) atomicAdd(&g_st[b*5+3], r);
    r = blockReduceD(q2,  sm); if (threadIdx.x == 0) atomicAdd(&g_st[b*5+4], r);
}

__global__ void k_fin_split() {
    int b = threadIdx.x;
    if (b >= NB) return;
    double N = (double)NPB;
    double m  = g_sumx[b] / N;
    double pos = g_st[b*5+0], s1 = g_st[b*5+1], q1 = g_st[b*5+2];
    double s2 = g_st[b*5+3], q2 = g_st[b*5+4];
    double neg = N - pos;
    double avg1 = 0, k1 = 0, avg2 = 0, k2 = 0;
    if (pos > 0) {
        avg1 = s1 / pos;
        double v1 = (q1 - s1*s1/pos) / N;
        k1 = sqrt(pos / N) / sqrt(v1 + 1e-5);
    }
    if (neg > 0) {
        avg2 = s2 / neg;
        double v2 = (q2 - s2*s2/neg) / N;
        k2 = sqrt(neg / N) / sqrt(v2 + 1e-5);
    }
    g_cst[b*5+0] = (float)m;
    g_cst[b*5+1] = (float)avg1;
    g_cst[b*5+2] = (float)k1;
    g_cst[b*5+3] = (float)avg2;
    g_cst[b*5+4] = (float)k2;
}

// ---------------- stage 3: fused split + hi/lo pack ----------------
__global__ __launch_bounds__(256) void k_split_pack(
    const float* __restrict__ x,
    const float* __restrict__ psc1, const float* __restrict__ psc2,
    const float* __restrict__ prc,  const float* __restrict__ pnc1,
    const float* __restrict__ pnc2)
{
    int i = blockIdx.x * 256 + threadIdx.x;
    if (i >= NB*NPAIR*HW) return;
    int pos = i & (HW-1);
    int bp = i >> 14;
    int b = bp / NPAIR, p = bp - b*NPAIR;
    float m = g_cst[b*5+0], avg1 = g_cst[b*5+1], k1 = g_cst[b*5+2];
    float avg2 = g_cst[b*5+3], k2 = g_cst[b*5+4];
    float sc1 = *psc1, sc2 = *psc2, rc = *prc, nc1 = *pnc1, nc2 = *pnc2;

    float x1v[2], x2v[2];
    #pragma unroll
    for (int c = 0; c < 2; c++) {
        size_t gi = ((size_t)b*NC + 2*p + c)*HW + pos;
        float xc = x[gi] - m;
        float xr, x1o, x2o;
        if (xc > 0.f) {
            float x1n = k1 * (xc - avg1);
            xr = 0.5f * nc1 * x1n + rc * xc;
            x1o = sc1 * xc + x1n;
            x2o = 0.f;
        } else {
            float x2n = k2 * (xc - avg2);
            xr = 0.5f * nc2 * x2n + rc * xc;
            x1o = 0.f;
            x2o = sc2 * xc + x2n;
        }
        g_xr[gi] = xr;
        g_x1o[gi] = x1o;
        x1v[c] = x1o;
        x2v[c] = x2o;
    }
    __half h10 = __float2half_rn(x1v[0]), h11 = __float2half_rn(x1v[1]);
    __half l10 = __float2half_rn(x1v[0] - __half2float(h10));
    __half l11 = __float2half_rn(x1v[1] - __half2float(h11));
    g_x1hl[i] = make_uint2(packh2(h10, h11), packh2(l10, l11));
    __half h20 = __float2half_rn(x2v[0]), h21 = __float2half_rn(x2v[1]);
    __half l20 = __float2half_rn(x2v[0] - __half2float(h20));
    __half l21 = __float2half_rn(x2v[1] - __half2float(h21));
    g_x2hl[i] = make_uint2(packh2(h20, h21), packh2(l20, l21));
}

// ---------------- pack fp32 -> hi/lo half pair-interleaved (val only) ------
__global__ __launch_bounds__(256) void k_pack_hl(
    const float* __restrict__ src, uint2* __restrict__ dst)
{
    int i = blockIdx.x * 256 + threadIdx.x;
    if (i >= NB*NPAIR*HW) return;
    int pos = i & (HW-1);
    int bp = i >> 14;
    int b = bp / NPAIR, p = bp - b*NPAIR;
    float v0 = src[((size_t)b*NC + 2*p)   * HW + pos];
    float v1 = src[((size_t)b*NC + 2*p+1) * HW + pos];
    __half h0 = __float2half_rn(v0);
    __half h1 = __float2half_rn(v1);
    __half l0 = __float2half_rn(v0 - __half2float(h0));
    __half l1 = __float2half_rn(v1 - __half2float(h1));
    dst[i] = make_uint2(packh2(h0, h1), packh2(l0, l1));
}

// ---------------- weight fragment prep ----------------
__global__ __launch_bounds__(256) void k_prep_wfrag(
    const float* __restrict__ w, uint4* __restrict__ dst,
    int nb, int wbStride)
{
    int idx = blockIdx.x * 256 + threadIdx.x;
    int total = nb * NCHUNK * 9 * 6 * 32;
    if (idx >= total) return;
    int lane = idx & 31; int r = idx >> 5;
    int mfrag = r % 6; r /= 6;
    int tap = r % 9; r /= 9;
    int chunk = r % NCHUNK; r /= NCHUNK;
    int b = r;
    int g = lane >> 2, t = lane & 3;
    const float* wb = w + (size_t)b * wbStride;

    float v[2][4];
    #pragma unroll
    for (int rr = 0; rr < 2; rr++) {
        int co = mfrag*16 + g + rr*8;
        #pragma unroll
        for (int cc = 0; cc < 4; cc++) {
            int ci = chunk*16 + 2*t + (cc>>1)*8 + (cc&1);
            v[rr][cc] = wb[((size_t)co*NC + ci)*KK + tap];
        }
    }
    __half h[2][4], l[2][4];
    #pragma unroll
    for (int rr = 0; rr < 2; rr++)
        #pragma unroll
        for (int cc = 0; cc < 4; cc++) {
            h[rr][cc] = __float2half_rn(v[rr][cc]);
            l[rr][cc] = __float2half_rn(v[rr][cc] - __half2float(h[rr][cc]));
        }
    uint4 hi4, lo4;
    hi4.x = packh2(h[0][0], h[0][1]);
    hi4.y = packh2(h[1][0], h[1][1]);
    hi4.z = packh2(h[0][2], h[0][3]);
    hi4.w = packh2(h[1][2], h[1][3]);
    lo4.x = packh2(l[0][0], l[0][1]);
    lo4.y = packh2(l[1][0], l[1][1]);
    lo4.z = packh2(l[0][2], l[0][3]);
    lo4.w = packh2(l[1][2], l[1][3]);
    size_t base = (((size_t)b*NCHUNK + chunk)*9 + tap);
    dst[((base*2 + 0)*6 + mfrag)*32 + lane] = hi4;
    dst[((base*2 + 1)*6 + mfrag)*32 + lane] = lo4;
}

// ---------------- tensor-core 3x3 conv ----------------
__device__ __forceinline__ void mma16816(float* d, const uint4& a, unsigned b0, unsigned b1) {
    asm volatile(
        "mma.sync.aligned.m16n8k16.row.col.f32.f16.f16.f32 "
        "{%0,%1,%2,%3}, {%4,%5,%6,%7}, {%8,%9}, {%0,%1,%2,%3};\n"
        : "+f"(d[0]), "+f"(d[1]), "+f"(d[2]), "+f"(d[3])
        : "r"(a.x), "r"(a.y), "r"(a.z), "r"(a.w), "r"(b0), "r"(b1));
}

__global__ __launch_bounds__(256) void k_conv_mma(
    const uint2* __restrict__ inHL, const uint4* __restrict__ wf,
    int wfBatchStride, float* __restrict__ outF)
{
    __shared__ unsigned sIn[3*130*24];               // 37440 bytes, static

    int hb = blockIdx.x, b = blockIdx.y;
    int tid = threadIdx.x, lane = tid & 31, wid = tid >> 5;
    int mhalf = wid >> 2, nq = wid & 3;
    int g = lane >> 2, t = lane & 3;
    int wbase = nq * 32;

    const uint2* inb = inHL + (size_t)b * NPAIR * HW;
    const uint4* wfb = wf + (size_t)b * wfBatchStride;

    float acc[3][4][4];
    #pragma unroll
    for (int m = 0; m < 3; m++)
        #pragma unroll
        for (int n = 0; n < 4; n++)
            #pragma unroll
            for (int j = 0; j < 4; j++) acc[m][n][j] = 0.f;

    for (int chunk = 0; chunk < NCHUNK; chunk++) {
        for (int i = tid; i < 3120; i += 256) {
            int pl = i / 390; int rem = i - pl*390;
            int r = rem / 130; int pix = rem - r*130;
            int h = hb + r - 1, w = pix - 1;
            uint2 v = make_uint2(0u, 0u);
            if (h >= 0 && h < HH && w >= 0 && w < WW)
                v = inb[((size_t)(chunk*8 + pl)*HH + h)*WW + w];
            *(uint2*)&sIn[(r*130 + pix)*24 + 2*pl] = v;
        }
        __syncthreads();

        const uint4* wchunk = wfb + (size_t)chunk * WFRAG_PER_CHUNK;
        #pragma unroll
        for (int tap = 0; tap < 9; tap++) {
            int kh = tap / 3, kw = tap - kh*3;
            const uint4* wtap = wchunk + tap*384;
            uint4 ah[3], al[3];
            #pragma unroll
            for (int m = 0; m < 3; m++) {
                ah[m] = __ldg(&wtap[(mhalf*3 + m)*32 + lane]);
                al[m] = __ldg(&wtap[192 + (mhalf*3 + m)*32 + lane]);
            }
            // R8 delta: preload all 4 n-frag B operands, then three passes
            // of 12 independent MMAs each (same-acc reuse separated by 11
            // independent MMAs instead of back-to-back).
            uint2 B0[4], B1[4];
            #pragma unroll
            for (int nf = 0; nf < 4; nf++) {
                int pix = wbase + nf*8 + g + kw;
                const unsigned* pb = sIn + (kh*130 + pix)*24;
                B0[nf] = *(const uint2*)(pb + 2*t);
                B1[nf] = *(const uint2*)(pb + 2*t + 8);
            }
            #pragma unroll
            for (int m = 0; m < 3; m++)
                #pragma unroll
                for (int nf = 0; nf < 4; nf++)
                    mma16816(acc[m][nf], ah[m], B0[nf].x, B1[nf].x); // hi*hi
            #pragma unroll
            for (int m = 0; m < 3; m++)
                #pragma unroll
                for (int nf = 0; nf < 4; nf++)
                    mma16816(acc[m][nf], ah[m], B0[nf].y, B1[nf].y); // hi_w*lo_x
            #pragma unroll
            for (int m = 0; m < 3; m++)
                #pragma unroll
                for (int nf = 0; nf < 4; nf++)
                    mma16816(acc[m][nf], al[m], B0[nf].x, B1[nf].x); // lo_w*hi_x
        }
        __syncthreads();
    }

    #pragma unroll
    for (int m = 0; m < 3; m++) {
        int co = mhalf*48 + m*16 + g;
        #pragma unroll
        for (int nf = 0; nf < 4; nf++) {
            int pix = wbase + nf*8 + 2*t;
            size_t o0 = ((size_t)(b*NC + co))*HW + hb*WW + pix;
            size_t o1 = ((size_t)(b*NC + co + 8))*HW + hb*WW + pix;
            *(float2*)&outF[o0] = make_float2(acc[m][nf][0], acc[m][nf][1]);
            *(float2*)&outF[o1] = make_float2(acc[m][nf][2], acc[m][nf][3]);
        }
    }
}

// ---------------- attention logits GEMM ----------------
__global__ __launch_bounds__(256) void k_attn_gemm(
    const float* __restrict__ key, const float* __restrict__ qry,
    float* __restrict__ attn)
{
    __shared__ float sQ[32][65];
    __shared__ float sK[32][65];
    int bz = blockIdx.z;
    int b = bz / 9, k = bz - b*9;
    int kh = k / 3, kw = k - kh*3;
    int qt = blockIdx.y, ct = blockIdx.x;
    int tid = threadIdx.x;
    int tq = tid >> 4, tc = tid & 15;
    const float* qb = qry + (size_t)(b*NC + qt*32)*HW;
    const float* kb = key + (size_t)(b*NC + ct*32)*HW;

    float a00 = 0, a01 = 0, a10 = 0, a11 = 0;
    for (int l0 = 0; l0 < LL; l0 += 64) {
        for (int idx = tid; idx < 2048; idx += 256) {
            int row = idx >> 6, j = idx & 63;
            int l = l0 + j;
            float qv = 0.f, kv = 0.f;
            if (l < LL) {
                int ho = l / 42, wo = l - ho*42;
                int off = (3*ho + kh)*WW + 3*wo + kw;
                qv = qb[(size_t)row*HW + off];
                kv = kb[(size_t)row*HW + off];
            }
            sQ[row][j] = qv;
            sK[row][j] = kv;
        }
        __syncthreads();
        #pragma unroll 8
        for (int j = 0; j < 64; j++) {
            float q0 = sQ[tq*2][j],   q1 = sQ[tq*2+1][j];
            float c0 = sK[tc*2][j],   c1 = sK[tc*2+1][j];
            a00 += q0*c0; a01 += q0*c1; a10 += q1*c0; a11 += q1*c1;
        }
        __syncthreads();
    }
    const float invs = 1.0f / sqrtf(864.0f);
    int q = qt*32 + tq*2, c = ct*32 + tc*2;
    float* ab = attn + (size_t)b*NC*CKK;
    ab[(size_t)q*CKK     + c*9     + k] = a00*invs;
    ab[(size_t)q*CKK     + (c+1)*9 + k] = a01*invs;
    ab[(size_t)(q+1)*CKK + c*9     + k] = a10*invs;
    ab[(size_t)(q+1)*CKK + (c+1)*9 + k] = a11*invs;
}

// ---------------- softmax over 864 per (b,q) ----------------
__global__ __launch_bounds__(256) void k_softmax(float* __restrict__ attn) {
    __shared__ float sm[256];
    int row = blockIdx.x;
    float* p = attn + (size_t)row*CKK;
    int t = threadIdx.x;

    float mx = -1e30f;
    for (int i = t; i < CKK; i += 256) mx = fmaxf(mx, p[i]);
    sm[t] = mx; __syncthreads();
    for (int s = 128; s > 0; s >>= 1) {
        if (t < s) sm[t] = fmaxf(sm[t], sm[t+s]);
        __syncthreads();
    }
    mx = sm[0]; __syncthreads();

    float s = 0.f;
    for (int i = t; i < CKK; i += 256) {
        float e = expf(p[i] - mx);
        p[i] = e;
        s += e;
    }
    sm[t] = s; __syncthreads();
    for (int st = 128; st > 0; st >>= 1) {
        if (t < st) sm[t] += sm[t+st];
        __syncthreads();
    }
    float inv = 1.0f / sm[0];
    for (int i = t; i < CKK; i += 256) p[i] *= inv;
}

// ---------------- LN stats (sum, sumsq) per batch ----------------
__global__ __launch_bounds__(256) void k_lnstats(const float* __restrict__ p, int slot) {
    __shared__ double sm[256];
    int b = blockIdx.y, c = blockIdx.x;
    const float* q = p + (size_t)(b*NC + c)*HW;
    double s = 0, ss = 0;
    for (int i = threadIdx.x; i < HW; i += 256) {
        double v = (double)q[i];
        s += v; ss += v*v;
    }
    double r;
    r = blockReduceD(s,  sm); if (threadIdx.x == 0) atomicAdd(&g_lnacc[(slot*NB + b)*2 + 0], r);
    r = blockReduceD(ss, sm); if (threadIdx.x == 0) atomicAdd(&g_lnacc[(slot*NB + b)*2 + 1], r);
}

__global__ void k_fin_ln() {
    int b = threadIdx.x;
    if (b >= NB) return;
    double N = (double)NPB;
    for (int slot = 0; slot < 2; slot++) {
        double s  = g_lnacc[(slot*NB + b)*2 + 0];
        double ss = g_lnacc[(slot*NB + b)*2 + 1];
        double m = s / N;
        double v = ss / N - m*m;
        g_lnc[b*4 + slot*2 + 0] = (float)m;
        g_lnc[b*4 + slot*2 + 1] = (float)(1.0 / sqrt(v + 1e-5));
    }
}

// ---------------- final fused: LN(y1p), LN(y2p)*x1o, 1x1 conv, +xr +bias ---
__global__ __launch_bounds__(256) void k_final(
    const float* __restrict__ wfull, const float* __restrict__ bfull,
    float* __restrict__ out)
{
    __shared__ float sV[16][128];
    __shared__ float sW[16][96];
    int blk = blockIdx.x;
    int b = blk >> 7;
    int px0 = (blk & 127) << 7;
    int tid = threadIdx.x;
    int to = tid >> 4, tp = tid & 15;

    float m1 = g_lnc[b*4+0], i1 = g_lnc[b*4+1];
    float m2 = g_lnc[b*4+2], i2 = g_lnc[b*4+3];

    float acc[6][8];
    #pragma unroll
    for (int c = 0; c < 6; c++)
        #pragma unroll
        for (int j = 0; j < 8; j++) acc[c][j] = 0.f;

    size_t base = (size_t)b*NC*HW + px0;

    for (int i0 = 0; i0 < 2*NC; i0 += 16) {
        for (int idx = tid; idx < 2048; idx += 256) {
            int ir = idx >> 7, pp = idx & 127;
            int i = i0 + ir;
            float v;
            if (i < NC) {
                v = (g_y1p[base + (size_t)i*HW + pp] - m1) * i1;
            } else {
                int jj = i - NC;
                v = (g_y2p[base + (size_t)jj*HW + pp] - m2) * i2
                    * g_x1o[base + (size_t)jj*HW + pp];
            }
            sV[ir][pp] = v;
        }
        for (int idx = tid; idx < 16*96; idx += 256) {
            int ir = idx / 96, o = idx - ir*96;
            sW[ir][o] = wfull[(size_t)o*(2*NC) + i0 + ir];
        }
        __syncthreads();
        #pragma unroll
        for (int ii = 0; ii < 16; ii++) {
            float wr[6], vr[8];
            #pragma unroll
            for (int c = 0; c < 6; c++) wr[c] = sW[ii][to*6 + c];
            #pragma unroll
            for (int j = 0; j < 8; j++) vr[j] = sV[ii][tp + j*16];
            #pragma unroll
            for (int c = 0; c < 6; c++)
                #pragma unroll
                for (int j = 0; j < 8; j++)
                    acc[c][j] += wr[c] * vr[j];
        }
        __syncthreads();
    }

    #pragma unroll
    for (int c = 0; c < 6; c++) {
        int o = to*6 + c;
        float bb = bfull[o];
        #pragma unroll
        for (int j = 0; j < 8; j++) {
            size_t gi = (size_t)(b*NC + o)*HW + px0 + tp + j*16;
            out[gi] = acc[c][j] + g_xr[gi] + bb;
        }
    }
}

// ---------------- launch ----------------
extern "C" void kernel_launch(void* const* d_in, const int* in_sizes, int n_in,
                              void* d_out, int out_size)
{
    const float* x       = (const float*)d_in[0];
    const float* w_conv2 = (const float*)d_in[1];
    const float* aw1     = (const float*)d_in[2];
    const float* aw2     = (const float*)d_in[3];
    const float* aw3     = (const float*)d_in[4];
    const float* w_full  = (const float*)d_in[5];
    const float* b_full  = (const float*)d_in[6];
    const float* sc1     = (const float*)d_in[7];
    const float* sc2     = (const float*)d_in[8];
    const float* res_c   = (const float*)d_in[9];
    const float* nc1     = (const float*)d_in[10];
    const float* nc2     = (const float*)d_in[11];
    float* out = (float*)d_out;

    float *p_key, *p_qry, *p_val, *p_y2p, *p_y1p, *p_attn;
    uint2 *p_x1hl, *p_x2hl, *p_valhl;
    uint4 *p_w1f, *p_w2f, *p_w3f, *p_wc2f, *p_attnf;
    cudaGetSymbolAddress((void**)&p_key, g_key);
    cudaGetSymbolAddress((void**)&p_qry, g_qry);
    cudaGetSymbolAddress((void**)&p_val, g_val);
    cudaGetSymbolAddress((void**)&p_y2p, g_y2p);
    cudaGetSymbolAddress((void**)&p_y1p, g_y1p);
    cudaGetSymbolAddress((void**)&p_attn, g_attn);
    cudaGetSymbolAddress((void**)&p_x1hl, g_x1hl);
    cudaGetSymbolAddress((void**)&p_x2hl, g_x2hl);
    cudaGetSymbolAddress((void**)&p_valhl, g_valhl);
    cudaGetSymbolAddress((void**)&p_w1f, g_w1f);
    cudaGetSymbolAddress((void**)&p_w2f, g_w2f);
    cudaGetSymbolAddress((void**)&p_w3f, g_w3f);
    cudaGetSymbolAddress((void**)&p_wc2f, g_wc2f);
    cudaGetSymbolAddress((void**)&p_attnf, g_attnf);

    dim3 redGrid(NC, NB);
    dim3 convGrid(HH, NB);
    int packBlocks = (NB*NPAIR*HW + 255)/256;

    k_zero<<<1, 64>>>();

    // weight fragment prep (depends only on inputs)
    int prepShared = (NCHUNK*9*6*32 + 255)/256;
    k_prep_wfrag<<<prepShared, 256>>>(aw1,     p_w1f,  1, 0);
    k_prep_wfrag<<<prepShared, 256>>>(aw2,     p_w2f,  1, 0);
    k_prep_wfrag<<<prepShared, 256>>>(aw3,     p_w3f,  1, 0);
    k_prep_wfrag<<<prepShared, 256>>>(w_conv2, p_wc2f, 1, 0);

    k_sum_x<<<redGrid, 256>>>(x);
    k_stats2<<<redGrid, 256>>>(x);
    k_fin_split<<<1, NB>>>();
    k_split_pack<<<packBlocks, 256>>>(x, sc1, sc2, res_c, nc1, nc2);

    // four shared-weight convs (tensor cores)
    k_conv_mma<<<convGrid, 256>>>(p_x1hl, p_w1f,  0, p_key);
    k_conv_mma<<<convGrid, 256>>>(p_x2hl, p_w2f,  0, p_qry);
    k_conv_mma<<<convGrid, 256>>>(p_x1hl, p_w3f,  0, p_val);
    k_conv_mma<<<convGrid, 256>>>(p_x2hl, p_wc2f, 0, p_y2p);

    // attention logits + softmax
    k_attn_gemm<<<dim3(3, 3, NB*9), 256>>>(p_key, p_qry, p_attn);
    k_softmax<<<NB*NC, 256>>>(p_attn);

    // pack value, prep per-example attention weights, attention conv
    k_pack_hl<<<packBlocks, 256>>>(p_val, p_valhl);
    int prepAttn = (NB*NCHUNK*9*6*32 + 255)/256;
    k_prep_wfrag<<<prepAttn, 256>>>(p_attn, p_attnf, NB, NC*CKK);
    k_conv_mma<<<convGrid, 256>>>(p_valhl, p_attnf, WFRAG_PER_B, p_y1p);

    // layer-norm stats for y1 and y2 paths
    k_lnstats<<<redGrid, 256>>>(p_y1p, 0);
    k_lnstats<<<redGrid, 256>>>(p_y2p, 1);
    k_fin_ln<<<1, NB>>>();

    // fused final
    k_final<<<NB*128, 256>>>(w_full, b_full, out);
}

// round 9
// speedup vs baseline: 1.0069x; 1.0069x over previous
// R9: R5 base (MMA order reverted per R8 measurement) + merged 4-conv launch
// (tail-wave elimination) + drop g_x1o + float4 reductions.
#include <cuda_runtime.h>
#include <cuda_fp16.h>
#include <math.h>
#include <stdint.h>

#define NB 8
#define NC 96
#define HH 128
#define WW 128
#define HW (HH*WW)
#define NPB (NC*HW)
#define NTOT (NB*NPB)
#define KK 9
#define CKK (NC*KK)          // 864
#define LL 1764

#define NPAIR 48
#define NCHUNK 6
#define WFRAG_PER_CHUNK 3456                   // 9*2*6*32 uint4
#define WFRAG_PER_B (NCHUNK*WFRAG_PER_CHUNK)   // 20736 uint4

// ---------------- scratch ----------------
__device__ float g_xr[NTOT];
__device__ float g_key[NTOT];
__device__ float g_qry[NTOT];
__device__ float g_val[NTOT];
__device__ float g_y2p[NTOT];
__device__ float g_y1p[NTOT];
__device__ float g_attn[NB*NC*CKK];

__device__ uint2 g_x1hl[NB*NPAIR*HW];
__device__ uint2 g_x2hl[NB*NPAIR*HW];
__device__ uint2 g_valhl[NB*NPAIR*HW];

__device__ uint4 g_w1f[WFRAG_PER_B];
__device__ uint4 g_w2f[WFRAG_PER_B];
__device__ uint4 g_w3f[WFRAG_PER_B];
__device__ uint4 g_wc2f[WFRAG_PER_B];
__device__ uint4 g_attnf[NB*WFRAG_PER_B];

__device__ double g_sumx[NB];
__device__ double g_st[NB*5];
__device__ double g_lnacc[2*NB*2];
__device__ float  g_cst[NB*5];
__device__ float  g_lnc[NB*4];

// ---------------- helpers ----------------
__device__ __forceinline__ double blockReduceD(double v, double* sm) {
    int t = threadIdx.x;
    __syncthreads();
    sm[t] = v;
    __syncthreads();
    for (int s = 128; s > 0; s >>= 1) {
        if (t < s) sm[t] += sm[t + s];
        __syncthreads();
    }
    return sm[0];
}

__device__ __forceinline__ unsigned packh2(__half a, __half b) {
    __half2 h = __halves2half2(a, b);
    return *reinterpret_cast<unsigned*>(&h);
}

// ---------------- stage 0: zero accumulators ----------------
__global__ void k_zero() {
    int i = threadIdx.x;
    if (i < NB) g_sumx[i] = 0.0;
    if (i < NB*5) g_st[i] = 0.0;
    if (i < 2*NB*2) g_lnacc[i] = 0.0;
}

// ---------------- per-batch sum of x (float4) ----------------
__global__ __launch_bounds__(256) void k_sum_x(const float* __restrict__ x) {
    __shared__ double sm[256];
    int b = blockIdx.y, c = blockIdx.x;
    const float4* p = (const float4*)(x + (size_t)(b*NC + c)*HW);
    double s = 0.0;
    for (int i = threadIdx.x; i < HW/4; i += 256) {
        float4 v = p[i];
        s += (double)((v.x + v.y) + (v.z + v.w));
    }
    double r = blockReduceD(s, sm);
    if (threadIdx.x == 0) atomicAdd(&g_sumx[b], r);
}

// ---------------- split stats (float4) ----------------
__global__ __launch_bounds__(256) void k_stats2(const float* __restrict__ x) {
    __shared__ double sm[256];
    int b = blockIdx.y, c = blockIdx.x;
    float m = (float)(g_sumx[b] / (double)NPB);
    const float4* p = (const float4*)(x + (size_t)(b*NC + c)*HW);
    double pos = 0, s1 = 0, q1 = 0, s2 = 0, q2 = 0;
    for (int i = threadIdx.x; i < HW/4; i += 256) {
        float4 v4 = p[i];
        float vv[4] = {v4.x, v4.y, v4.z, v4.w};
        #pragma unroll
        for (int j = 0; j < 4; j++) {
            float xc = vv[j] - m;
            if (xc > 0.f) { pos += 1.0; s1 += (double)xc; q1 += (double)xc*(double)xc; }
            else          { s2 += (double)xc; q2 += (double)xc*(double)xc; }
        }
    }
    double r;
    r = blockReduceD(pos, sm); if (threadIdx.x == 0) atomicAdd(&g_st[b*5+0], r);
    r = blockReduceD(s1,  sm); if (threadIdx.x == 0) atomicAdd(&g_st[b*5+1], r);
    r = blockReduceD(q1,  sm); if (threadIdx.x == 0) atomicAdd(&g_st[b*5+2], r);
    r = blockReduceD(s2,  sm); if (threadIdx.x == 0) atomicAdd(&g_st[b*5+3], r);
    r = blockReduceD(q2,  sm); if (threadIdx.x == 0) atomicAdd(&g_st[b*5+4], r);
}

__global__ void k_fin_split() {
    int b = threadIdx.x;
    if (b >= NB) return;
    double N = (double)NPB;
    double m  = g_sumx[b] / N;
    double pos = g_st[b*5+0], s1 = g_st[b*5+1], q1 = g_st[b*5+2];
    double s2 = g_st[b*5+3], q2 = g_st[b*5+4];
    double neg = N - pos;
    double avg1 = 0, k1 = 0, avg2 = 0, k2 = 0;
    if (pos > 0) {
        avg1 = s1 / pos;
        double v1 = (q1 - s1*s1/pos) / N;
        k1 = sqrt(pos / N) / sqrt(v1 + 1e-5);
    }
    if (neg > 0) {
        avg2 = s2 / neg;
        double v2 = (q2 - s2*s2/neg) / N;
        k2 = sqrt(neg / N) / sqrt(v2 + 1e-5);
    }
    g_cst[b*5+0] = (float)m;
    g_cst[b*5+1] = (float)avg1;
    g_cst[b*5+2] = (float)k1;
    g_cst[b*5+3] = (float)avg2;
    g_cst[b*5+4] = (float)k2;
}

// ---------------- fused split + hi/lo pack (no fp32 x1o store) -------------
__global__ __launch_bounds__(256) void k_split_pack(
    const float* __restrict__ x,
    const float* __restrict__ psc1, const float* __restrict__ psc2,
    const float* __restrict__ prc,  const float* __restrict__ pnc1,
    const float* __restrict__ pnc2)
{
    int i = blockIdx.x * 256 + threadIdx.x;
    if (i >= NB*NPAIR*HW) return;
    int pos = i & (HW-1);
    int bp = i >> 14;
    int b = bp / NPAIR, p = bp - b*NPAIR;
    float m = g_cst[b*5+0], avg1 = g_cst[b*5+1], k1 = g_cst[b*5+2];
    float avg2 = g_cst[b*5+3], k2 = g_cst[b*5+4];
    float sc1 = *psc1, sc2 = *psc2, rc = *prc, nc1 = *pnc1, nc2 = *pnc2;

    float x1v[2], x2v[2];
    #pragma unroll
    for (int c = 0; c < 2; c++) {
        size_t gi = ((size_t)b*NC + 2*p + c)*HW + pos;
        float xc = x[gi] - m;
        float xr, x1o, x2o;
        if (xc > 0.f) {
            float x1n = k1 * (xc - avg1);
            xr = 0.5f * nc1 * x1n + rc * xc;
            x1o = sc1 * xc + x1n;
            x2o = 0.f;
        } else {
            float x2n = k2 * (xc - avg2);
            xr = 0.5f * nc2 * x2n + rc * xc;
            x1o = 0.f;
            x2o = sc2 * xc + x2n;
        }
        g_xr[gi] = xr;
        x1v[c] = x1o;
        x2v[c] = x2o;
    }
    __half h10 = __float2half_rn(x1v[0]), h11 = __float2half_rn(x1v[1]);
    __half l10 = __float2half_rn(x1v[0] - __half2float(h10));
    __half l11 = __float2half_rn(x1v[1] - __half2float(h11));
    g_x1hl[i] = make_uint2(packh2(h10, h11), packh2(l10, l11));
    __half h20 = __float2half_rn(x2v[0]), h21 = __float2half_rn(x2v[1]);
    __half l20 = __float2half_rn(x2v[0] - __half2float(h20));
    __half l21 = __float2half_rn(x2v[1] - __half2float(h21));
    g_x2hl[i] = make_uint2(packh2(h20, h21), packh2(l20, l21));
}

// ---------------- pack fp32 -> hi/lo (val) ----------------
__global__ __launch_bounds__(256) void k_pack_hl(
    const float* __restrict__ src, uint2* __restrict__ dst)
{
    int i = blockIdx.x * 256 + threadIdx.x;
    if (i >= NB*NPAIR*HW) return;
    int pos = i & (HW-1);
    int bp = i >> 14;
    int b = bp / NPAIR, p = bp - b*NPAIR;
    float v0 = src[((size_t)b*NC + 2*p)   * HW + pos];
    float v1 = src[((size_t)b*NC + 2*p+1) * HW + pos];
    __half h0 = __float2half_rn(v0);
    __half h1 = __float2half_rn(v1);
    __half l0 = __float2half_rn(v0 - __half2float(h0));
    __half l1 = __float2half_rn(v1 - __half2float(h1));
    dst[i] = make_uint2(packh2(h0, h1), packh2(l0, l1));
}

// ---------------- weight fragment prep ----------------
__global__ __launch_bounds__(256) void k_prep_wfrag(
    const float* __restrict__ w, uint4* __restrict__ dst,
    int nb, int wbStride)
{
    int idx = blockIdx.x * 256 + threadIdx.x;
    int total = nb * NCHUNK * 9 * 6 * 32;
    if (idx >= total) return;
    int lane = idx & 31; int r = idx >> 5;
    int mfrag = r % 6; r /= 6;
    int tap = r % 9; r /= 9;
    int chunk = r % NCHUNK; r /= NCHUNK;
    int b = r;
    int g = lane >> 2, t = lane & 3;
    const float* wb = w + (size_t)b * wbStride;

    float v[2][4];
    #pragma unroll
    for (int rr = 0; rr < 2; rr++) {
        int co = mfrag*16 + g + rr*8;
        #pragma unroll
        for (int cc = 0; cc < 4; cc++) {
            int ci = chunk*16 + 2*t + (cc>>1)*8 + (cc&1);
            v[rr][cc] = wb[((size_t)co*NC + ci)*KK + tap];
        }
    }
    __half h[2][4], l[2][4];
    #pragma unroll
    for (int rr = 0; rr < 2; rr++)
        #pragma unroll
        for (int cc = 0; cc < 4; cc++) {
            h[rr][cc] = __float2half_rn(v[rr][cc]);
            l[rr][cc] = __float2half_rn(v[rr][cc] - __half2float(h[rr][cc]));
        }
    uint4 hi4, lo4;
    hi4.x = packh2(h[0][0], h[0][1]);
    hi4.y = packh2(h[1][0], h[1][1]);
    hi4.z = packh2(h[0][2], h[0][3]);
    hi4.w = packh2(h[1][2], h[1][3]);
    lo4.x = packh2(l[0][0], l[0][1]);
    lo4.y = packh2(l[1][0], l[1][1]);
    lo4.z = packh2(l[0][2], l[0][3]);
    lo4.w = packh2(l[1][2], l[1][3]);
    size_t base = (((size_t)b*NCHUNK + chunk)*9 + tap);
    dst[((base*2 + 0)*6 + mfrag)*32 + lane] = hi4;
    dst[((base*2 + 1)*6 + mfrag)*32 + lane] = lo4;
}

// ---------------- tensor-core 3x3 conv core (R5 MMA order) ----------------
__device__ __forceinline__ void mma16816(float* d, const uint4& a, unsigned b0, unsigned b1) {
    asm volatile(
        "mma.sync.aligned.m16n8k16.row.col.f32.f16.f16.f32 "
        "{%0,%1,%2,%3}, {%4,%5,%6,%7}, {%8,%9}, {%0,%1,%2,%3};\n"
        : "+f"(d[0]), "+f"(d[1]), "+f"(d[2]), "+f"(d[3])
        : "r"(a.x), "r"(a.y), "r"(a.z), "r"(a.w), "r"(b0), "r"(b1));
}

__device__ __forceinline__ void conv_mma_body(
    const uint2* __restrict__ inb, const uint4* __restrict__ wfb,
    float* __restrict__ outF, int hb, int b)
{
    __shared__ unsigned sIn[3*130*24];               // 37440 bytes, static

    int tid = threadIdx.x, lane = tid & 31, wid = tid >> 5;
    int mhalf = wid >> 2, nq = wid & 3;
    int g = lane >> 2, t = lane & 3;
    int wbase = nq * 32;

    float acc[3][4][4];
    #pragma unroll
    for (int m = 0; m < 3; m++)
        #pragma unroll
        for (int n = 0; n < 4; n++)
            #pragma unroll
            for (int j = 0; j < 4; j++) acc[m][n][j] = 0.f;

    for (int chunk = 0; chunk < NCHUNK; chunk++) {
        for (int i = tid; i < 3120; i += 256) {
            int pl = i / 390; int rem = i - pl*390;
            int r = rem / 130; int pix = rem - r*130;
            int h = hb + r - 1, w = pix - 1;
            uint2 v = make_uint2(0u, 0u);
            if (h >= 0 && h < HH && w >= 0 && w < WW)
                v = inb[((size_t)(chunk*8 + pl)*HH + h)*WW + w];
            *(uint2*)&sIn[(r*130 + pix)*24 + 2*pl] = v;
        }
        __syncthreads();

        const uint4* wchunk = wfb + (size_t)chunk * WFRAG_PER_CHUNK;
        #pragma unroll
        for (int tap = 0; tap < 9; tap++) {
            int kh = tap / 3, kw = tap - kh*3;
            const uint4* wtap = wchunk + tap*384;
            uint4 ah[3], al[3];
            #pragma unroll
            for (int m = 0; m < 3; m++) {
                ah[m] = __ldg(&wtap[(mhalf*3 + m)*32 + lane]);
                al[m] = __ldg(&wtap[192 + (mhalf*3 + m)*32 + lane]);
            }
            #pragma unroll
            for (int nf = 0; nf < 4; nf++) {
                int pix = wbase + nf*8 + g + kw;
                const unsigned* pb = sIn + (kh*130 + pix)*24;
                uint2 B0 = *(const uint2*)(pb + 2*t);
                uint2 B1 = *(const uint2*)(pb + 2*t + 8);
                #pragma unroll
                for (int m = 0; m < 3; m++) {
                    mma16816(acc[m][nf], ah[m], B0.x, B1.x); // hi*hi
                    mma16816(acc[m][nf], ah[m], B0.y, B1.y); // hi_w*lo_x
                    mma16816(acc[m][nf], al[m], B0.x, B1.x); // lo_w*hi_x
                }
            }
        }
        __syncthreads();
    }

    #pragma unroll
    for (int m = 0; m < 3; m++) {
        int co = mhalf*48 + m*16 + g;
        #pragma unroll
        for (int nf = 0; nf < 4; nf++) {
            int pix = wbase + nf*8 + 2*t;
            size_t o0 = ((size_t)(b*NC + co))*HW + hb*WW + pix;
            size_t o1 = ((size_t)(b*NC + co + 8))*HW + hb*WW + pix;
            *(float2*)&outF[o0] = make_float2(acc[m][nf][0], acc[m][nf][1]);
            *(float2*)&outF[o1] = make_float2(acc[m][nf][2], acc[m][nf][3]);
        }
    }
}

// merged 4-conv launch: z = sel*NB + b
__global__ __launch_bounds__(256) void k_conv4(
    const uint2* __restrict__ x1hl, const uint2* __restrict__ x2hl,
    const uint4* __restrict__ w1f,  const uint4* __restrict__ w2f,
    const uint4* __restrict__ w3f,  const uint4* __restrict__ wc2f,
    float* __restrict__ keyO, float* __restrict__ qryO,
    float* __restrict__ valO, float* __restrict__ y2pO)
{
    int z = blockIdx.z;
    int sel = z >> 3, b = z & 7;
    const uint2* in = (sel == 0 || sel == 2) ? x1hl : x2hl;
    const uint4* wf = (sel == 0) ? w1f : (sel == 1) ? w2f : (sel == 2) ? w3f : wc2f;
    float* out = (sel == 0) ? keyO : (sel == 1) ? qryO : (sel == 2) ? valO : y2pO;
    conv_mma_body(in + (size_t)b * NPAIR * HW, wf, out, blockIdx.x, b);
}

// single conv (per-example attention weights)
__global__ __launch_bounds__(256) void k_conv_mma(
    const uint2* __restrict__ inHL, const uint4* __restrict__ wf,
    float* __restrict__ outF)
{
    int b = blockIdx.y;
    conv_mma_body(inHL + (size_t)b * NPAIR * HW,
                  wf + (size_t)b * WFRAG_PER_B, outF, blockIdx.x, b);
}

// ---------------- attention logits GEMM ----------------
__global__ __launch_bounds__(256) void k_attn_gemm(
    const float* __restrict__ key, const float* __restrict__ qry,
    float* __restrict__ attn)
{
    __shared__ float sQ[32][65];
    __shared__ float sK[32][65];
    int bz = blockIdx.z;
    int b = bz / 9, k = bz - b*9;
    int kh = k / 3, kw = k - kh*3;
    int qt = blockIdx.y, ct = blockIdx.x;
    int tid = threadIdx.x;
    int tq = tid >> 4, tc = tid & 15;
    const float* qb = qry + (size_t)(b*NC + qt*32)*HW;
    const float* kb = key + (size_t)(b*NC + ct*32)*HW;

    float a00 = 0, a01 = 0, a10 = 0, a11 = 0;
    for (int l0 = 0; l0 < LL; l0 += 64) {
        for (int idx = tid; idx < 2048; idx += 256) {
            int row = idx >> 6, j = idx & 63;
            int l = l0 + j;
            float qv = 0.f, kv = 0.f;
            if (l < LL) {
                int ho = l / 42, wo = l - ho*42;
                int off = (3*ho + kh)*WW + 3*wo + kw;
                qv = qb[(size_t)row*HW + off];
                kv = kb[(size_t)row*HW + off];
            }
            sQ[row][j] = qv;
            sK[row][j] = kv;
        }
        __syncthreads();
        #pragma unroll 8
        for (int j = 0; j < 64; j++) {
            float q0 = sQ[tq*2][j],   q1 = sQ[tq*2+1][j];
            float c0 = sK[tc*2][j],   c1 = sK[tc*2+1][j];
            a00 += q0*c0; a01 += q0*c1; a10 += q1*c0; a11 += q1*c1;
        }
        __syncthreads();
    }
    const float invs = 1.0f / sqrtf(864.0f);
    int q = qt*32 + tq*2, c = ct*32 + tc*2;
    float* ab = attn + (size_t)b*NC*CKK;
    ab[(size_t)q*CKK     + c*9     + k] = a00*invs;
    ab[(size_t)q*CKK     + (c+1)*9 + k] = a01*invs;
    ab[(size_t)(q+1)*CKK + c*9     + k] = a10*invs;
    ab[(size_t)(q+1)*CKK + (c+1)*9 + k] = a11*invs;
}

// ---------------- softmax ----------------
__global__ __launch_bounds__(256) void k_softmax(float* __restrict__ attn) {
    __shared__ float sm[256];
    int row = blockIdx.x;
    float* p = attn + (size_t)row*CKK;
    int t = threadIdx.x;

    float mx = -1e30f;
    for (int i = t; i < CKK; i += 256) mx = fmaxf(mx, p[i]);
    sm[t] = mx; __syncthreads();
    for (int s = 128; s > 0; s >>= 1) {
        if (t < s) sm[t] = fmaxf(sm[t], sm[t+s]);
        __syncthreads();
    }
    mx = sm[0]; __syncthreads();

    float s = 0.f;
    for (int i = t; i < CKK; i += 256) {
        float e = expf(p[i] - mx);
        p[i] = e;
        s += e;
    }
    sm[t] = s; __syncthreads();
    for (int st = 128; st > 0; st >>= 1) {
        if (t < st) sm[t] += sm[t+st];
        __syncthreads();
    }
    float inv = 1.0f / sm[0];
    for (int i = t; i < CKK; i += 256) p[i] *= inv;
}

// ---------------- LN stats (float4) ----------------
__global__ __launch_bounds__(256) void k_lnstats(const float* __restrict__ p, int slot) {
    __shared__ double sm[256];
    int b = blockIdx.y, c = blockIdx.x;
    const float4* q = (const float4*)(p + (size_t)(b*NC + c)*HW);
    double s = 0, ss = 0;
    for (int i = threadIdx.x; i < HW/4; i += 256) {
        float4 v4 = q[i];
        double a = v4.x, bb = v4.y, cc = v4.z, d = v4.w;
        s += (a + bb) + (cc + d);
        ss += (a*a + bb*bb) + (cc*cc + d*d);
    }
    double r;
    r = blockReduceD(s,  sm); if (threadIdx.x == 0) atomicAdd(&g_lnacc[(slot*NB + b)*2 + 0], r);
    r = blockReduceD(ss, sm); if (threadIdx.x == 0) atomicAdd(&g_lnacc[(slot*NB + b)*2 + 1], r);
}

__global__ void k_fin_ln() {
    int b = threadIdx.x;
    if (b >= NB) return;
    double N = (double)NPB;
    for (int slot = 0; slot < 2; slot++) {
        double s  = g_lnacc[(slot*NB + b)*2 + 0];
        double ss = g_lnacc[(slot*NB + b)*2 + 1];
        double m = s / N;
        double v = ss / N - m*m;
        g_lnc[b*4 + slot*2 + 0] = (float)m;
        g_lnc[b*4 + slot*2 + 1] = (float)(1.0 / sqrt(v + 1e-5));
    }
}

// ---------------- final fused ----------------
__global__ __launch_bounds__(256) void k_final(
    const float* __restrict__ wfull, const float* __restrict__ bfull,
    float* __restrict__ out)
{
    __shared__ float sV[16][128];
    __shared__ float sW[16][96];
    int blk = blockIdx.x;
    int b = blk >> 7;
    int px0 = (blk & 127) << 7;
    int tid = threadIdx.x;
    int to = tid >> 4, tp = tid & 15;

    float m1 = g_lnc[b*4+0], i1 = g_lnc[b*4+1];
    float m2 = g_lnc[b*4+2], i2 = g_lnc[b*4+3];

    float acc[6][8];
    #pragma unroll
    for (int c = 0; c < 6; c++)
        #pragma unroll
        for (int j = 0; j < 8; j++) acc[c][j] = 0.f;

    size_t base = (size_t)b*NC*HW + px0;

    for (int i0 = 0; i0 < 2*NC; i0 += 16) {
        for (int idx = tid; idx < 2048; idx += 256) {
            int ir = idx >> 7, pp = idx & 127;
            int i = i0 + ir;
            float v;
            if (i < NC) {
                v = (g_y1p[base + (size_t)i*HW + pp] - m1) * i1;
            } else {
                int jj = i - NC;
                // gate = x1o reconstructed exactly as hi+lo from g_x1hl
                uint2 hl = g_x1hl[(((size_t)b*NPAIR + (jj>>1)) << 14) + px0 + pp];
                __half2 hih = *reinterpret_cast<__half2*>(&hl.x);
                __half2 loh = *reinterpret_cast<__half2*>(&hl.y);
                float gate = (jj & 1)
                    ? (__high2float(hih) + __high2float(loh))
                    : (__low2float(hih) + __low2float(loh));
                v = (g_y2p[base + (size_t)jj*HW + pp] - m2) * i2 * gate;
            }
            sV[ir][pp] = v;
        }
        for (int idx = tid; idx < 16*96; idx += 256) {
            int ir = idx / 96, o = idx - ir*96;
            sW[ir][o] = wfull[(size_t)o*(2*NC) + i0 + ir];
        }
        __syncthreads();
        #pragma unroll
        for (int ii = 0; ii < 16; ii++) {
            float wr[6], vr[8];
            #pragma unroll
            for (int c = 0; c < 6; c++) wr[c] = sW[ii][to*6 + c];
            #pragma unroll
            for (int j = 0; j < 8; j++) vr[j] = sV[ii][tp + j*16];
            #pragma unroll
            for (int c = 0; c < 6; c++)
                #pragma unroll
                for (int j = 0; j < 8; j++)
                    acc[c][j] += wr[c] * vr[j];
        }
        __syncthreads();
    }

    #pragma unroll
    for (int c = 0; c < 6; c++) {
        int o = to*6 + c;
        float bb = bfull[o];
        #pragma unroll
        for (int j = 0; j < 8; j++) {
            size_t gi = (size_t)(b*NC + o)*HW + px0 + tp + j*16;
            out[gi] = acc[c][j] + g_xr[gi] + bb;
        }
    }
}

// ---------------- launch ----------------
extern "C" void kernel_launch(void* const* d_in, const int* in_sizes, int n_in,
                              void* d_out, int out_size)
{
    const float* x       = (const float*)d_in[0];
    const float* w_conv2 = (const float*)d_in[1];
    const float* aw1     = (const float*)d_in[2];
    const float* aw2     = (const float*)d_in[3];
    const float* aw3     = (const float*)d_in[4];
    const float* w_full  = (const float*)d_in[5];
    const float* b_full  = (const float*)d_in[6];
    const float* sc1     = (const float*)d_in[7];
    const float* sc2     = (const float*)d_in[8];
    const float* res_c   = (const float*)d_in[9];
    const float* nc1     = (const float*)d_in[10];
    const float* nc2     = (const float*)d_in[11];
    float* out = (float*)d_out;

    float *p_key, *p_qry, *p_val, *p_y2p, *p_y1p, *p_attn;
    uint2 *p_x1hl, *p_x2hl, *p_valhl;
    uint4 *p_w1f, *p_w2f, *p_w3f, *p_wc2f, *p_attnf;
    cudaGetSymbolAddress((void**)&p_key, g_key);
    cudaGetSymbolAddress((void**)&p_qry, g_qry);
    cudaGetSymbolAddress((void**)&p_val, g_val);
    cudaGetSymbolAddress((void**)&p_y2p, g_y2p);
    cudaGetSymbolAddress((void**)&p_y1p, g_y1p);
    cudaGetSymbolAddress((void**)&p_attn, g_attn);
    cudaGetSymbolAddress((void**)&p_x1hl, g_x1hl);
    cudaGetSymbolAddress((void**)&p_x2hl, g_x2hl);
    cudaGetSymbolAddress((void**)&p_valhl, g_valhl);
    cudaGetSymbolAddress((void**)&p_w1f, g_w1f);
    cudaGetSymbolAddress((void**)&p_w2f, g_w2f);
    cudaGetSymbolAddress((void**)&p_w3f, g_w3f);
    cudaGetSymbolAddress((void**)&p_wc2f, g_wc2f);
    cudaGetSymbolAddress((void**)&p_attnf, g_attnf);

    dim3 redGrid(NC, NB);
    int packBlocks = (NB*NPAIR*HW + 255)/256;

    k_zero<<<1, 64>>>();

    int prepShared = (NCHUNK*9*6*32 + 255)/256;
    k_prep_wfrag<<<prepShared, 256>>>(aw1,     p_w1f,  1, 0);
    k_prep_wfrag<<<prepShared, 256>>>(aw2,     p_w2f,  1, 0);
    k_prep_wfrag<<<prepShared, 256>>>(aw3,     p_w3f,  1, 0);
    k_prep_wfrag<<<prepShared, 256>>>(w_conv2, p_wc2f, 1, 0);

    k_sum_x<<<redGrid, 256>>>(x);
    k_stats2<<<redGrid, 256>>>(x);
    k_fin_split<<<1, NB>>>();
    k_split_pack<<<packBlocks, 256>>>(x, sc1, sc2, res_c, nc1, nc2);

    // merged 4 shared-weight convs in one launch (tail-wave elimination)
    k_conv4<<<dim3(HH, 1, 4*NB), 256>>>(p_x1hl, p_x2hl,
                                        p_w1f, p_w2f, p_w3f, p_wc2f,
                                        p_key, p_qry, p_val, p_y2p);

    k_attn_gemm<<<dim3(3, 3, NB*9), 256>>>(p_key, p_qry, p_attn);
    k_softmax<<<NB*NC, 256>>>(p_attn);

    k_pack_hl<<<packBlocks, 256>>>(p_val, p_valhl);
    int prepAttn = (NB*NCHUNK*9*6*32 + 255)/256;
    k_prep_wfrag<<<prepAttn, 256>>>(p_attn, p_attnf, NB, NC*CKK);
    k_conv_mma<<<dim3(HH, NB), 256>>>(p_valhl, p_attnf, p_y1p);

    k_lnstats<<<redGrid, 256>>>(p_y1p, 0);
    k_lnstats<<<redGrid, 256>>>(p_y2p, 1);
    k_fin_ln<<<1, NB>>>();

    k_final<<<NB*128, 256>>>(w_full, b_full, out);
}

// round 13
// speedup vs baseline: 1.3437x; 1.3344x over previous
// R13: R12 with the smem fix — sIn hoisted to kernel scope (one 37,440B
// array per kernel) and passed into the templated conv body. ptxas was
// summing per-instantiation static __shared__ (74,880B > 48KB limit).
#include <cuda_runtime.h>
#include <cuda_fp16.h>
#include <math.h>
#include <stdint.h>

#define NB 8
#define NC 96
#define HH 128
#define WW 128
#define HW (HH*WW)
#define NPB (NC*HW)
#define NTOT (NB*NPB)
#define KK 9
#define CKK (NC*KK)          // 864
#define LL 1764

#define NPAIR 48
#define NCHUNK 6
#define WFRAG_PER_CHUNK 3456                   // 9*2*6*32 uint4
#define WFRAG_PER_B (NCHUNK*WFRAG_PER_CHUNK)   // 20736 uint4

// ---------------- scratch ----------------
__device__ float g_xr[NTOT];
__device__ float g_key[NTOT];
__device__ float g_qry[NTOT];
__device__ float g_val[NTOT];
__device__ float g_y2p[NTOT];
__device__ float g_y1p[NTOT];
__device__ float g_attn[NB*NC*CKK];

__device__ uint2 g_x1hl[NB*NPAIR*HW];
__device__ uint2 g_x2hl[NB*NPAIR*HW];
__device__ uint2 g_valhl[NB*NPAIR*HW];

__device__ uint4 g_w1f[WFRAG_PER_B];
__device__ uint4 g_w2f[WFRAG_PER_B];
__device__ uint4 g_w3f[WFRAG_PER_B];
__device__ uint4 g_wc2f[WFRAG_PER_B];
__device__ uint4 g_attnf[NB*WFRAG_PER_B];

__device__ double g_sumx[NB];
__device__ double g_st[NB*5];
__device__ double g_lnacc[2*NB*2];
__device__ float  g_cst[NB*5];
__device__ float  g_lnc[NB*4];

// ---------------- helpers ----------------
__device__ __forceinline__ double blockReduceD(double v, double* sm) {
    int t = threadIdx.x;
    __syncthreads();
    sm[t] = v;
    __syncthreads();
    for (int s = 128; s > 0; s >>= 1) {
        if (t < s) sm[t] += sm[t + s];
        __syncthreads();
    }
    return sm[0];
}

__device__ __forceinline__ unsigned packh2(__half a, __half b) {
    __half2 h = __halves2half2(a, b);
    return *reinterpret_cast<unsigned*>(&h);
}

// ---------------- stage 0: zero accumulators ----------------
__global__ void k_zero() {
    int i = threadIdx.x;
    if (i < NB) g_sumx[i] = 0.0;
    if (i < NB*5) g_st[i] = 0.0;
    if (i < 2*NB*2) g_lnacc[i] = 0.0;
}

// ---------------- per-batch sum of x (float4) ----------------
__global__ __launch_bounds__(256) void k_sum_x(const float* __restrict__ x) {
    __shared__ double sm[256];
    int b = blockIdx.y, c = blockIdx.x;
    const float4* p = (const float4*)(x + (size_t)(b*NC + c)*HW);
    double s = 0.0;
    for (int i = threadIdx.x; i < HW/4; i += 256) {
        float4 v = p[i];
        s += (double)((v.x + v.y) + (v.z + v.w));
    }
    double r = blockReduceD(s, sm);
    if (threadIdx.x == 0) atomicAdd(&g_sumx[b], r);
}

// ---------------- split stats (float4) ----------------
__global__ __launch_bounds__(256) void k_stats2(const float* __restrict__ x) {
    __shared__ double sm[256];
    int b = blockIdx.y, c = blockIdx.x;
    float m = (float)(g_sumx[b] / (double)NPB);
    const float4* p = (const float4*)(x + (size_t)(b*NC + c)*HW);
    double pos = 0, s1 = 0, q1 = 0, s2 = 0, q2 = 0;
    for (int i = threadIdx.x; i < HW/4; i += 256) {
        float4 v4 = p[i];
        float vv[4] = {v4.x, v4.y, v4.z, v4.w};
        #pragma unroll
        for (int j = 0; j < 4; j++) {
            float xc = vv[j] - m;
            if (xc > 0.f) { pos += 1.0; s1 += (double)xc; q1 += (double)xc*(double)xc; }
            else          { s2 += (double)xc; q2 += (double)xc*(double)xc; }
        }
    }
    double r;
    r = blockReduceD(pos, sm); if (threadIdx.x == 0) atomicAdd(&g_st[b*5+0], r);
    r = blockReduceD(s1,  sm); if (threadIdx.x == 0) atomicAdd(&g_st[b*5+1], r);
    r = blockReduceD(q1,  sm); if (threadIdx.x == 0) atomicAdd(&g_st[b*5+2], r);
    r = blockReduceD(s2,  sm); if (threadIdx.x == 0) atomicAdd(&g_st[b*5+3], r);
    r = blockReduceD(q2,  sm); if (threadIdx.x == 0) atomicAdd(&g_st[b*5+4], r);
}

__global__ void k_fin_split() {
    int b = threadIdx.x;
    if (b >= NB) return;
    double N = (double)NPB;
    double m  = g_sumx[b] / N;
    double pos = g_st[b*5+0], s1 = g_st[b*5+1], q1 = g_st[b*5+2];
    double s2 = g_st[b*5+3], q2 = g_st[b*5+4];
    double neg = N - pos;
    double avg1 = 0, k1 = 0, avg2 = 0, k2 = 0;
    if (pos > 0) {
        avg1 = s1 / pos;
        double v1 = (q1 - s1*s1/pos) / N;
        k1 = sqrt(pos / N) / sqrt(v1 + 1e-5);
    }
    if (neg > 0) {
        avg2 = s2 / neg;
        double v2 = (q2 - s2*s2/neg) / N;
        k2 = sqrt(neg / N) / sqrt(v2 + 1e-5);
    }
    g_cst[b*5+0] = (float)m;
    g_cst[b*5+1] = (float)avg1;
    g_cst[b*5+2] = (float)k1;
    g_cst[b*5+3] = (float)avg2;
    g_cst[b*5+4] = (float)k2;
}

// ---------------- fused split + hi/lo pack (no fp32 x1o store) -------------
__global__ __launch_bounds__(256) void k_split_pack(
    const float* __restrict__ x,
    const float* __restrict__ psc1, const float* __restrict__ psc2,
    const float* __restrict__ prc,  const float* __restrict__ pnc1,
    const float* __restrict__ pnc2)
{
    int i = blockIdx.x * 256 + threadIdx.x;
    if (i >= NB*NPAIR*HW) return;
    int pos = i & (HW-1);
    int bp = i >> 14;
    int b = bp / NPAIR, p = bp - b*NPAIR;
    float m = g_cst[b*5+0], avg1 = g_cst[b*5+1], k1 = g_cst[b*5+2];
    float avg2 = g_cst[b*5+3], k2 = g_cst[b*5+4];
    float sc1 = *psc1, sc2 = *psc2, rc = *prc, nc1 = *pnc1, nc2 = *pnc2;

    float x1v[2], x2v[2];
    #pragma unroll
    for (int c = 0; c < 2; c++) {
        size_t gi = ((size_t)b*NC + 2*p + c)*HW + pos;
        float xc = x[gi] - m;
        float xr, x1o, x2o;
        if (xc > 0.f) {
            float x1n = k1 * (xc - avg1);
            xr = 0.5f * nc1 * x1n + rc * xc;
            x1o = sc1 * xc + x1n;
            x2o = 0.f;
        } else {
            float x2n = k2 * (xc - avg2);
            xr = 0.5f * nc2 * x2n + rc * xc;
            x1o = 0.f;
            x2o = sc2 * xc + x2n;
        }
        g_xr[gi] = xr;
        x1v[c] = x1o;
        x2v[c] = x2o;
    }
    __half h10 = __float2half_rn(x1v[0]), h11 = __float2half_rn(x1v[1]);
    __half l10 = __float2half_rn(x1v[0] - __half2float(h10));
    __half l11 = __float2half_rn(x1v[1] - __half2float(h11));
    g_x1hl[i] = make_uint2(packh2(h10, h11), packh2(l10, l11));
    __half h20 = __float2half_rn(x2v[0]), h21 = __float2half_rn(x2v[1]);
    __half l20 = __float2half_rn(x2v[0] - __half2float(h20));
    __half l21 = __float2half_rn(x2v[1] - __half2float(h21));
    g_x2hl[i] = make_uint2(packh2(h20, h21), packh2(l20, l21));
}

// ---------------- pack fp32 -> hi/lo (val) ----------------
__global__ __launch_bounds__(256) void k_pack_hl(
    const float* __restrict__ src, uint2* __restrict__ dst)
{
    int i = blockIdx.x * 256 + threadIdx.x;
    if (i >= NB*NPAIR*HW) return;
    int pos = i & (HW-1);
    int bp = i >> 14;
    int b = bp / NPAIR, p = bp - b*NPAIR;
    float v0 = src[((size_t)b*NC + 2*p)   * HW + pos];
    float v1 = src[((size_t)b*NC + 2*p+1) * HW + pos];
    __half h0 = __float2half_rn(v0);
    __half h1 = __float2half_rn(v1);
    __half l0 = __float2half_rn(v0 - __half2float(h0));
    __half l1 = __float2half_rn(v1 - __half2float(h1));
    dst[i] = make_uint2(packh2(h0, h1), packh2(l0, l1));
}

// ---------------- weight fragment prep ----------------
__global__ __launch_bounds__(256) void k_prep_wfrag(
    const float* __restrict__ w, uint4* __restrict__ dst,
    int nb, int wbStride)
{
    int idx = blockIdx.x * 256 + threadIdx.x;
    int total = nb * NCHUNK * 9 * 6 * 32;
    if (idx >= total) return;
    int lane = idx & 31; int r = idx >> 5;
    int mfrag = r % 6; r /= 6;
    int tap = r % 9; r /= 9;
    int chunk = r % NCHUNK; r /= NCHUNK;
    int b = r;
    int g = lane >> 2, t = lane & 3;
    const float* wb = w + (size_t)b * wbStride;

    float v[2][4];
    #pragma unroll
    for (int rr = 0; rr < 2; rr++) {
        int co = mfrag*16 + g + rr*8;
        #pragma unroll
        for (int cc = 0; cc < 4; cc++) {
            int ci = chunk*16 + 2*t + (cc>>1)*8 + (cc&1);
            v[rr][cc] = wb[((size_t)co*NC + ci)*KK + tap];
        }
    }
    __half h[2][4], l[2][4];
    #pragma unroll
    for (int rr = 0; rr < 2; rr++)
        #pragma unroll
        for (int cc = 0; cc < 4; cc++) {
            h[rr][cc] = __float2half_rn(v[rr][cc]);
            l[rr][cc] = __float2half_rn(v[rr][cc] - __half2float(h[rr][cc]));
        }
    uint4 hi4, lo4;
    hi4.x = packh2(h[0][0], h[0][1]);
    hi4.y = packh2(h[1][0], h[1][1]);
    hi4.z = packh2(h[0][2], h[0][3]);
    hi4.w = packh2(h[1][2], h[1][3]);
    lo4.x = packh2(l[0][0], l[0][1]);
    lo4.y = packh2(l[1][0], l[1][1]);
    lo4.z = packh2(l[0][2], l[0][3]);
    lo4.w = packh2(l[1][2], l[1][3]);
    size_t base = (((size_t)b*NCHUNK + chunk)*9 + tap);
    dst[((base*2 + 0)*6 + mfrag)*32 + lane] = hi4;
    dst[((base*2 + 1)*6 + mfrag)*32 + lane] = lo4;
}

// ---------------- tensor-core 3x3 conv core, templated on MMA count -------
// sIn is declared ONCE at kernel scope and passed in (avoids per-template-
// instantiation static smem duplication).
__device__ __forceinline__ void mma16816(float* d, const uint4& a, unsigned b0, unsigned b1) {
    asm volatile(
        "mma.sync.aligned.m16n8k16.row.col.f32.f16.f16.f32 "
        "{%0,%1,%2,%3}, {%4,%5,%6,%7}, {%8,%9}, {%0,%1,%2,%3};\n"
        : "+f"(d[0]), "+f"(d[1]), "+f"(d[2]), "+f"(d[3])
        : "r"(a.x), "r"(a.y), "r"(a.z), "r"(a.w), "r"(b0), "r"(b1));
}

template<int NMMA>
__device__ __forceinline__ void conv_mma_body(
    unsigned* __restrict__ sIn,
    const uint2* __restrict__ inb, const uint4* __restrict__ wfb,
    float* __restrict__ outF, int hb, int b)
{
    int tid = threadIdx.x, lane = tid & 31, wid = tid >> 5;
    int mhalf = wid >> 2, nq = wid & 3;
    int g = lane >> 2, t = lane & 3;
    int wbase = nq * 32;

    float acc[3][4][4];
    #pragma unroll
    for (int m = 0; m < 3; m++)
        #pragma unroll
        for (int n = 0; n < 4; n++)
            #pragma unroll
            for (int j = 0; j < 4; j++) acc[m][n][j] = 0.f;

    for (int chunk = 0; chunk < NCHUNK; chunk++) {
        for (int i = tid; i < 3120; i += 256) {
            int pl = i / 390; int rem = i - pl*390;
            int r = rem / 130; int pix = rem - r*130;
            int h = hb + r - 1, w = pix - 1;
            uint2 v = make_uint2(0u, 0u);
            if (h >= 0 && h < HH && w >= 0 && w < WW)
                v = inb[((size_t)(chunk*8 + pl)*HH + h)*WW + w];
            *(uint2*)&sIn[(r*130 + pix)*24 + 2*pl] = v;
        }
        __syncthreads();

        const uint4* wchunk = wfb + (size_t)chunk * WFRAG_PER_CHUNK;
        #pragma unroll
        for (int tap = 0; tap < 9; tap++) {
            int kh = tap / 3, kw = tap - kh*3;
            const uint4* wtap = wchunk + tap*384;
            uint4 ah[3], al[3];
            #pragma unroll
            for (int m = 0; m < 3; m++) {
                ah[m] = __ldg(&wtap[(mhalf*3 + m)*32 + lane]);
                if (NMMA == 3)
                    al[m] = __ldg(&wtap[192 + (mhalf*3 + m)*32 + lane]);
            }
            #pragma unroll
            for (int nf = 0; nf < 4; nf++) {
                int pix = wbase + nf*8 + g + kw;
                const unsigned* pb = sIn + (kh*130 + pix)*24;
                if (NMMA == 3) {
                    uint2 B0 = *(const uint2*)(pb + 2*t);
                    uint2 B1 = *(const uint2*)(pb + 2*t + 8);
                    #pragma unroll
                    for (int m = 0; m < 3; m++) {
                        mma16816(acc[m][nf], ah[m], B0.x, B1.x); // hi*hi
                        mma16816(acc[m][nf], ah[m], B0.y, B1.y); // hi_w*lo_x
                        mma16816(acc[m][nf], al[m], B0.x, B1.x); // lo_w*hi_x
                    }
                } else {
                    unsigned b0 = pb[2*t];
                    unsigned b1 = pb[2*t + 8];
                    #pragma unroll
                    for (int m = 0; m < 3; m++)
                        mma16816(acc[m][nf], ah[m], b0, b1);     // hi*hi only
                }
            }
        }
        __syncthreads();
    }

    #pragma unroll
    for (int m = 0; m < 3; m++) {
        int co = mhalf*48 + m*16 + g;
        #pragma unroll
        for (int nf = 0; nf < 4; nf++) {
            int pix = wbase + nf*8 + 2*t;
            size_t o0 = ((size_t)(b*NC + co))*HW + hb*WW + pix;
            size_t o1 = ((size_t)(b*NC + co + 8))*HW + hb*WW + pix;
            *(float2*)&outF[o0] = make_float2(acc[m][nf][0], acc[m][nf][1]);
            *(float2*)&outF[o1] = make_float2(acc[m][nf][2], acc[m][nf][3]);
        }
    }
}

// merged 4-conv launch: z = sel*NB + b. key/qry NMMA=3, val/y2p NMMA=1.
__global__ __launch_bounds__(256) void k_conv4(
    const uint2* __restrict__ x1hl, const uint2* __restrict__ x2hl,
    const uint4* __restrict__ w1f,  const uint4* __restrict__ w2f,
    const uint4* __restrict__ w3f,  const uint4* __restrict__ wc2f,
    float* __restrict__ keyO, float* __restrict__ qryO,
    float* __restrict__ valO, float* __restrict__ y2pO)
{
    __shared__ unsigned sIn[3*130*24];               // 37440 B, single array
    int z = blockIdx.z;
    int sel = z >> 3, b = z & 7;
    const uint2* in = (sel == 0 || sel == 2) ? x1hl : x2hl;
    const uint4* wf = (sel == 0) ? w1f : (sel == 1) ? w2f : (sel == 2) ? w3f : wc2f;
    float* out = (sel == 0) ? keyO : (sel == 1) ? qryO : (sel == 2) ? valO : y2pO;
    const uint2* inb = in + (size_t)b * NPAIR * HW;
    if (sel < 2) conv_mma_body<3>(sIn, inb, wf, out, blockIdx.x, b);
    else         conv_mma_body<1>(sIn, inb, wf, out, blockIdx.x, b);
}

// single conv (per-example attention weights), NMMA=1
__global__ __launch_bounds__(256) void k_conv_mma(
    const uint2* __restrict__ inHL, const uint4* __restrict__ wf,
    float* __restrict__ outF)
{
    __shared__ unsigned sIn[3*130*24];
    int b = blockIdx.y;
    conv_mma_body<1>(sIn, inHL + (size_t)b * NPAIR * HW,
                     wf + (size_t)b * WFRAG_PER_B, outF, blockIdx.x, b);
}

// ---------------- attention logits GEMM ----------------
__global__ __launch_bounds__(256) void k_attn_gemm(
    const float* __restrict__ key, const float* __restrict__ qry,
    float* __restrict__ attn)
{
    __shared__ float sQ[32][65];
    __shared__ float sK[32][65];
    int bz = blockIdx.z;
    int b = bz / 9, k = bz - b*9;
    int kh = k / 3, kw = k - kh*3;
    int qt = blockIdx.y, ct = blockIdx.x;
    int tid = threadIdx.x;
    int tq = tid >> 4, tc = tid & 15;
    const float* qb = qry + (size_t)(b*NC + qt*32)*HW;
    const float* kb = key + (size_t)(b*NC + ct*32)*HW;

    float a00 = 0, a01 = 0, a10 = 0, a11 = 0;
    for (int l0 = 0; l0 < LL; l0 += 64) {
        for (int idx = tid; idx < 2048; idx += 256) {
            int row = idx >> 6, j = idx & 63;
            int l = l0 + j;
            float qv = 0.f, kv = 0.f;
            if (l < LL) {
                int ho = l / 42, wo = l - ho*42;
                int off = (3*ho + kh)*WW + 3*wo + kw;
                qv = qb[(size_t)row*HW + off];
                kv = kb[(size_t)row*HW + off];
            }
            sQ[row][j] = qv;
            sK[row][j] = kv;
        }
        __syncthreads();
        #pragma unroll 8
        for (int j = 0; j < 64; j++) {
            float q0 = sQ[tq*2][j],   q1 = sQ[tq*2+1][j];
            float c0 = sK[tc*2][j],   c1 = sK[tc*2+1][j];
            a00 += q0*c0; a01 += q0*c1; a10 += q1*c0; a11 += q1*c1;
        }
        __syncthreads();
    }
    const float invs = 1.0f / sqrtf(864.0f);
    int q = qt*32 + tq*2, c = ct*32 + tc*2;
    float* ab = attn + (size_t)b*NC*CKK;
    ab[(size_t)q*CKK     + c*9     + k] = a00*invs;
    ab[(size_t)q*CKK     + (c+1)*9 + k] = a01*invs;
    ab[(size_t)(q+1)*CKK + c*9     + k] = a10*invs;
    ab[(size_t)(q+1)*CKK + (c+1)*9 + k] = a11*invs;
}

// ---------------- softmax ----------------
__global__ __launch_bounds__(256) void k_softmax(float* __restrict__ attn) {
    __shared__ float sm[256];
    int row = blockIdx.x;
    float* p = attn + (size_t)row*CKK;
    int t = threadIdx.x;

    float mx = -1e30f;
    for (int i = t; i < CKK; i += 256) mx = fmaxf(mx, p[i]);
    sm[t] = mx; __syncthreads();
    for (int s = 128; s > 0; s >>= 1) {
        if (t < s) sm[t] = fmaxf(sm[t], sm[t+s]);
        __syncthreads();
    }
    mx = sm[0]; __syncthreads();

    float s = 0.f;
    for (int i = t; i < CKK; i += 256) {
        float e = expf(p[i] - mx);
        p[i] = e;
        s += e;
    }
    sm[t] = s; __syncthreads();
    for (int st = 128; st > 0; st >>= 1) {
        if (t < st) sm[t] += sm[t+st];
        __syncthreads();
    }
    float inv = 1.0f / sm[0];
    for (int i = t; i < CKK; i += 256) p[i] *= inv;
}

// ---------------- LN stats (float4) ----------------
__global__ __launch_bounds__(256) void k_lnstats(const float* __restrict__ p, int slot) {
    __shared__ double sm[256];
    int b = blockIdx.y, c = blockIdx.x;
    const float4* q = (const float4*)(p + (size_t)(b*NC + c)*HW);
    double s = 0, ss = 0;
    for (int i = threadIdx.x; i < HW/4; i += 256) {
        float4 v4 = q[i];
        double a = v4.x, bb = v4.y, cc = v4.z, d = v4.w;
        s += (a + bb) + (cc + d);
        ss += (a*a + bb*bb) + (cc*cc + d*d);
    }
    double r;
    r = blockReduceD(s,  sm); if (threadIdx.x == 0) atomicAdd(&g_lnacc[(slot*NB + b)*2 + 0], r);
    r = blockReduceD(ss, sm); if (threadIdx.x == 0) atomicAdd(&g_lnacc[(slot*NB + b)*2 + 1], r);
}

__global__ void k_fin_ln() {
    int b = threadIdx.x;
    if (b >= NB) return;
    double N = (double)NPB;
    for (int slot = 0; slot < 2; slot++) {
        double s  = g_lnacc[(slot*NB + b)*2 + 0];
        double ss = g_lnacc[(slot*NB + b)*2 + 1];
        double m = s / N;
        double v = ss / N - m*m;
        g_lnc[b*4 + slot*2 + 0] = (float)m;
        g_lnc[b*4 + slot*2 + 1] = (float)(1.0 / sqrt(v + 1e-5));
    }
}

// ---------------- final fused ----------------
__global__ __launch_bounds__(256) void k_final(
    const float* __restrict__ wfull, const float* __restrict__ bfull,
    float* __restrict__ out)
{
    __shared__ float sV[16][128];
    __shared__ float sW[16][96];
    int blk = blockIdx.x;
    int b = blk >> 7;
    int px0 = (blk & 127) << 7;
    int tid = threadIdx.x;
    int to = tid >> 4, tp = tid & 15;

    float m1 = g_lnc[b*4+0], i1 = g_lnc[b*4+1];
    float m2 = g_lnc[b*4+2], i2 = g_lnc[b*4+3];

    float acc[6][8];
    #pragma unroll
    for (int c = 0; c < 6; c++)
        #pragma unroll
        for (int j = 0; j < 8; j++) acc[c][j] = 0.f;

    size_t base = (size_t)b*NC*HW + px0;

    for (int i0 = 0; i0 < 2*NC; i0 += 16) {
        for (int idx = tid; idx < 2048; idx += 256) {
            int ir = idx >> 7, pp = idx & 127;
            int i = i0 + ir;
            float v;
            if (i < NC) {
                v = (g_y1p[base + (size_t)i*HW + pp] - m1) * i1;
            } else {
                int jj = i - NC;
                // gate = x1o reconstructed exactly as hi+lo from g_x1hl
                uint2 hl = g_x1hl[(((size_t)b*NPAIR + (jj>>1)) << 14) + px0 + pp];
                __half2 hih = *reinterpret_cast<__half2*>(&hl.x);
                __half2 loh = *reinterpret_cast<__half2*>(&hl.y);
                float gate = (jj & 1)
                    ? (__high2float(hih) + __high2float(loh))
                    : (__low2float(hih) + __low2float(loh));
                v = (g_y2p[base + (size_t)jj*HW + pp] - m2) * i2 * gate;
            }
            sV[ir][pp] = v;
        }
        for (int idx = tid; idx < 16*96; idx += 256) {
            int ir = idx / 96, o = idx - ir*96;
            sW[ir][o] = wfull[(size_t)o*(2*NC) + i0 + ir];
        }
        __syncthreads();
        #pragma unroll
        for (int ii = 0; ii < 16; ii++) {
            float wr[6], vr[8];
            #pragma unroll
            for (int c = 0; c < 6; c++) wr[c] = sW[ii][to*6 + c];
            #pragma unroll
            for (int j = 0; j < 8; j++) vr[j] = sV[ii][tp + j*16];
            #pragma unroll
            for (int c = 0; c < 6; c++)
                #pragma unroll
                for (int j = 0; j < 8; j++)
                    acc[c][j] += wr[c] * vr[j];
        }
        __syncthreads();
    }

    #pragma unroll
    for (int c = 0; c < 6; c++) {
        int o = to*6 + c;
        float bb = bfull[o];
        #pragma unroll
        for (int j = 0; j < 8; j++) {
            size_t gi = (size_t)(b*NC + o)*HW + px0 + tp + j*16;
            out[gi] = acc[c][j] + g_xr[gi] + bb;
        }
    }
}

// ---------------- launch ----------------
extern "C" void kernel_launch(void* const* d_in, const int* in_sizes, int n_in,
                              void* d_out, int out_size)
{
    const float* x       = (const float*)d_in[0];
    const float* w_conv2 = (const float*)d_in[1];
    const float* aw1     = (const float*)d_in[2];
    const float* aw2     = (const float*)d_in[3];
    const float* aw3     = (const float*)d_in[4];
    const float* w_full  = (const float*)d_in[5];
    const float* b_full  = (const float*)d_in[6];
    const float* sc1     = (const float*)d_in[7];
    const float* sc2     = (const float*)d_in[8];
    const float* res_c   = (const float*)d_in[9];
    const float* nc1     = (const float*)d_in[10];
    const float* nc2     = (const float*)d_in[11];
    float* out = (float*)d_out;

    float *p_key, *p_qry, *p_val, *p_y2p, *p_y1p, *p_attn;
    uint2 *p_x1hl, *p_x2hl, *p_valhl;
    uint4 *p_w1f, *p_w2f, *p_w3f, *p_wc2f, *p_attnf;
    cudaGetSymbolAddress((void**)&p_key, g_key);
    cudaGetSymbolAddress((void**)&p_qry, g_qry);
    cudaGetSymbolAddress((void**)&p_val, g_val);
    cudaGetSymbolAddress((void**)&p_y2p, g_y2p);
    cudaGetSymbolAddress((void**)&p_y1p, g_y1p);
    cudaGetSymbolAddress((void**)&p_attn, g_attn);
    cudaGetSymbolAddress((void**)&p_x1hl, g_x1hl);
    cudaGetSymbolAddress((void**)&p_x2hl, g_x2hl);
    cudaGetSymbolAddress((void**)&p_valhl, g_valhl);
    cudaGetSymbolAddress((void**)&p_w1f, g_w1f);
    cudaGetSymbolAddress((void**)&p_w2f, g_w2f);
    cudaGetSymbolAddress((void**)&p_w3f, g_w3f);
    cudaGetSymbolAddress((void**)&p_wc2f, g_wc2f);
    cudaGetSymbolAddress((void**)&p_attnf, g_attnf);

    dim3 redGrid(NC, NB);
    int packBlocks = (NB*NPAIR*HW + 255)/256;

    k_zero<<<1, 64>>>();

    int prepShared = (NCHUNK*9*6*32 + 255)/256;
    k_prep_wfrag<<<prepShared, 256>>>(aw1,     p_w1f,  1, 0);
    k_prep_wfrag<<<prepShared, 256>>>(aw2,     p_w2f,  1, 0);
    k_prep_wfrag<<<prepShared, 256>>>(aw3,     p_w3f,  1, 0);
    k_prep_wfrag<<<prepShared, 256>>>(w_conv2, p_wc2f, 1, 0);

    k_sum_x<<<redGrid, 256>>>(x);
    k_stats2<<<redGrid, 256>>>(x);
    k_fin_split<<<1, NB>>>();
    k_split_pack<<<packBlocks, 256>>>(x, sc1, sc2, res_c, nc1, nc2);

    // merged 4 shared-weight convs in one launch
    k_conv4<<<dim3(HH, 1, 4*NB), 256>>>(p_x1hl, p_x2hl,
                                        p_w1f, p_w2f, p_w3f, p_wc2f,
                                        p_key, p_qry, p_val, p_y2p);

    k_attn_gemm<<<dim3(3, 3, NB*9), 256>>>(p_key, p_qry, p_attn);
    k_softmax<<<NB*NC, 256>>>(p_attn);

    k_pack_hl<<<packBlocks, 256>>>(p_val, p_valhl);
    int prepAttn = (NB*NCHUNK*9*6*32 + 255)/256;
    k_prep_wfrag<<<prepAttn, 256>>>(p_attn, p_attnf, NB, NC*CKK);
    k_conv_mma<<<dim3(HH, NB), 256>>>(p_valhl, p_attnf, p_y1p);

    k_lnstats<<<redGrid, 256>>>(p_y1p, 0);
    k_lnstats<<<redGrid, 256>>>(p_y2p, 1);
    k_fin_ln<<<1, NB>>>();

    k_final<<<NB*128, 256>>>(w_full, b_full, out);
}